// round 6
// baseline (speedup 1.0000x reference)
#include <cuda_runtime.h>
#include <cuda_bf16.h>
#include <cstdint>

#define HEAD_NUM 8
#define DIM_QK 64
#define DIM_V 64
#define SPAN 64
#define STRIDE 4
#define R_SPAN 16

#define BATCH 2
#define MAX_LQ 4096
#define MAX_LKV 1024
#define DMODEL 512
#define GK 1536          // 3 * DMODEL (split-K concatenation)
#define CHUNKS 24        // GK / 64
#define WSTRIDE (DMODEL * GK)

// ---------------------------------------------------------------------------
// Scratch (no cudaMalloc allowed)
// ---------------------------------------------------------------------------
__device__ __align__(16) __nv_bfloat16 g_Ab[BATCH * MAX_LQ * GK];    // q-split, then ctx-split
__device__ __align__(16) __nv_bfloat16 g_Kb[BATCH * MAX_LKV * GK];   // k-split
__device__ __align__(16) __nv_bfloat16 g_Vb[BATCH * MAX_LKV * GK];   // v-split
__device__ __align__(16) __nv_bfloat16 g_Wb4[4 * WSTRIDE];           // 4 weight splits
__device__ __align__(16) float g_Q[BATCH * MAX_LQ * DMODEL];
__device__ __align__(16) float g_K[BATCH * MAX_LKV * DMODEL];
__device__ __align__(16) float g_V[BATCH * MAX_LKV * DMODEL];

// ---------------------------------------------------------------------------
// Baseline-target PTX helpers
// ---------------------------------------------------------------------------
__device__ __forceinline__ uint32_t smem_u32(const void* p) {
    uint32_t a;
    asm("{ .reg .u64 t; cvta.to.shared.u64 t, %1; cvt.u32.u64 %0, t; }" : "=r"(a) : "l"(p));
    return a;
}
__device__ __forceinline__ void cp_async16(uint32_t saddr, const void* gaddr) {
    asm volatile("cp.async.cg.shared.global [%0], [%1], 16;" :: "r"(saddr), "l"(gaddr));
}
__device__ __forceinline__ void cp_commit() { asm volatile("cp.async.commit_group;" ::: "memory"); }
__device__ __forceinline__ void cp_wait1() { asm volatile("cp.async.wait_group 1;" ::: "memory"); }
__device__ __forceinline__ void cp_wait0() { asm volatile("cp.async.wait_group 0;" ::: "memory"); }
__device__ __forceinline__ void ldm_x4(uint32_t* r, uint32_t addr) {
    asm volatile("ldmatrix.sync.aligned.m8n8.x4.shared.b16 {%0,%1,%2,%3}, [%4];"
                 : "=r"(r[0]), "=r"(r[1]), "=r"(r[2]), "=r"(r[3]) : "r"(addr));
}
__device__ __forceinline__ void ldm_x2(uint32_t* r, uint32_t addr) {
    asm volatile("ldmatrix.sync.aligned.m8n8.x2.shared.b16 {%0,%1}, [%2];"
                 : "=r"(r[0]), "=r"(r[1]) : "r"(addr));
}
__device__ __forceinline__ void mma_bf16(float* c, const uint32_t* a, const uint32_t* b) {
    asm volatile("mma.sync.aligned.m16n8k16.row.col.f32.bf16.bf16.f32 "
                 "{%0,%1,%2,%3}, {%4,%5,%6,%7}, {%8,%9}, {%0,%1,%2,%3};"
                 : "+f"(c[0]), "+f"(c[1]), "+f"(c[2]), "+f"(c[3])
                 : "r"(a[0]), "r"(a[1]), "r"(a[2]), "r"(a[3]), "r"(b[0]), "r"(b[1]));
}
__device__ __forceinline__ uint32_t sw128(uint32_t off) { return off ^ ((off >> 3) & 0x70); }

// ---------------------------------------------------------------------------
// GEMM tile worker: C[128,128] += A'[row0.., GK] * Bt'[col0.., GK]^T
// 3-stage cp.async pipeline, ONE __syncthreads per K-chunk.
// smem: stage s -> A @ s*32KB, B @ s*32KB+16KB. Total 96 KB.
// ---------------------------------------------------------------------------
#define STAGE_BYTES 32768u
#define GEMM_SMEM (3 * STAGE_BYTES)

__device__ __forceinline__ void issue_chunk(const __nv_bfloat16* __restrict__ A,
                                            const __nv_bfloat16* __restrict__ Bt,
                                            uint32_t sb, int row0, int col0,
                                            int chunk, int stage, int tid) {
    const int k0 = chunk * 64;
    const uint32_t aoff = stage * STAGE_BYTES;
    const uint32_t boff = aoff + 16384u;
    #pragma unroll
    for (int p = 0; p < 4; p++) {
        const int idx = tid + p * 256;
        const int r = idx >> 3;
        const int c8 = idx & 7;
        const uint32_t sw = sw128((uint32_t)(r * 128 + c8 * 16));
        cp_async16(sb + aoff + sw, A + (size_t)(row0 + r) * GK + k0 + c8 * 8);
        cp_async16(sb + boff + sw, Bt + (size_t)(col0 + r) * GK + k0 + c8 * 8);
    }
    cp_commit();
}

__device__ __forceinline__ void gemm_tile(const __nv_bfloat16* __restrict__ A,
                                          const __nv_bfloat16* __restrict__ Bt,
                                          float* __restrict__ C,
                                          int row0, int col0, uint32_t sb, int tid) {
    const int wid = tid >> 5, lane = tid & 31;
    const int warpM = wid >> 2, warpN = wid & 3;

    float acc[4][4][4];
    #pragma unroll
    for (int mi = 0; mi < 4; mi++)
        #pragma unroll
        for (int ni = 0; ni < 4; ni++)
            #pragma unroll
            for (int j = 0; j < 4; j++) acc[mi][ni][j] = 0.f;

    const int a_row_in_warp = lane & 15;
    const int a_khalf = (lane >> 4) & 1;
    const int b_row_in_tile = lane & 7;
    const int b_khalf = (lane >> 3) & 1;

    // prefetch 2 chunks
    issue_chunk(A, Bt, sb, row0, col0, 0, 0, tid);
    issue_chunk(A, Bt, sb, row0, col0, 1, 1, tid);

    int stage = 0, nstage = 2;
    for (int i = 0; i < CHUNKS; i++) {
        // chunk i's group must be complete
        if (i + 1 < CHUNKS) cp_wait1(); else cp_wait0();
        __syncthreads();   // all warps done with the buffer nstage will overwrite

        if (i + 2 < CHUNKS) {
            issue_chunk(A, Bt, sb, row0, col0, i + 2, nstage, tid);
            nstage = (nstage + 1 == 3) ? 0 : nstage + 1;
        }

        const uint32_t aoff = stage * STAGE_BYTES;
        const uint32_t boff = aoff + 16384u;
        #pragma unroll
        for (int kk = 0; kk < 4; kk++) {
            uint32_t afrag[4][4], bfrag[4][2];
            #pragma unroll
            for (int mi = 0; mi < 4; mi++) {
                const int r = warpM * 64 + mi * 16 + a_row_in_warp;
                ldm_x4(afrag[mi], sb + aoff + sw128((uint32_t)(r * 128 + kk * 32 + a_khalf * 16)));
            }
            #pragma unroll
            for (int ni = 0; ni < 4; ni++) {
                const int r = warpN * 32 + ni * 8 + b_row_in_tile;
                ldm_x2(bfrag[ni], sb + boff + sw128((uint32_t)(r * 128 + kk * 32 + b_khalf * 16)));
            }
            #pragma unroll
            for (int mi = 0; mi < 4; mi++)
                #pragma unroll
                for (int ni = 0; ni < 4; ni++)
                    mma_bf16(acc[mi][ni], afrag[mi], bfrag[ni]);
        }
        stage = (stage + 1 == 3) ? 0 : stage + 1;
    }

    const int erow = lane >> 2;
    const int ecol = 2 * (lane & 3);
    #pragma unroll
    for (int mi = 0; mi < 4; mi++) {
        #pragma unroll
        for (int ni = 0; ni < 4; ni++) {
            const int r = row0 + warpM * 64 + mi * 16 + erow;
            const int c = col0 + warpN * 32 + ni * 8 + ecol;
            *(float2*)(C + (size_t)r * DMODEL + c) = make_float2(acc[mi][ni][0], acc[mi][ni][1]);
            *(float2*)(C + (size_t)(r + 8) * DMODEL + c) = make_float2(acc[mi][ni][2], acc[mi][ni][3]);
        }
    }
}

__global__ __launch_bounds__(256) void gemm_qkv(const __nv_bfloat16* __restrict__ Aq,
                                                const __nv_bfloat16* __restrict__ Ak,
                                                const __nv_bfloat16* __restrict__ Av,
                                                const __nv_bfloat16* __restrict__ Wb,
                                                float* __restrict__ Cq,
                                                float* __restrict__ Ck,
                                                float* __restrict__ Cv) {
    extern __shared__ __align__(1024) char smem[];
    int t = blockIdx.x;
    const __nv_bfloat16 *A, *B;
    float* C;
    if (t < 256) { A = Aq; B = Wb; C = Cq; }
    else if (t < 320) { t -= 256; A = Ak; B = Wb + WSTRIDE; C = Ck; }
    else { t -= 320; A = Av; B = Wb + 2 * WSTRIDE; C = Cv; }
    gemm_tile(A, B, C, (t >> 2) * 128, (t & 3) * 128, smem_u32(smem), threadIdx.x);
}

__global__ __launch_bounds__(256) void gemm_one(const __nv_bfloat16* __restrict__ A,
                                                const __nv_bfloat16* __restrict__ Bt,
                                                float* __restrict__ C) {
    extern __shared__ __align__(1024) char smem[];
    gemm_tile(A, Bt, C, blockIdx.y * 128, blockIdx.x * 128, smem_u32(smem), threadIdx.x);
}

// ---------------------------------------------------------------------------
// Split conversions
// ---------------------------------------------------------------------------
struct __align__(8) bf4 { __nv_bfloat16 a, b, c, d; };

__device__ __forceinline__ void split1(float x, __nv_bfloat16& h, __nv_bfloat16& l) {
    h = __float2bfloat16(x);
    l = __float2bfloat16(x - __bfloat162float(h));
}

__global__ __launch_bounds__(256) void split_act_all(const float4* __restrict__ q,
                                                     const float4* __restrict__ k,
                                                     const float4* __restrict__ v,
                                                     __nv_bfloat16* __restrict__ outq,
                                                     __nv_bfloat16* __restrict__ outk,
                                                     __nv_bfloat16* __restrict__ outv,
                                                     int Mq, int Mkv) {
    const int gid = blockIdx.x * 256 + threadIdx.x;
    const int nq = Mq * 128, nkv = Mkv * 128;
    const float4* src;
    __nv_bfloat16* out;
    int loc;
    if (gid < nq) { src = q; out = outq; loc = gid; }
    else if (gid < nq + nkv) { src = k; out = outk; loc = gid - nq; }
    else if (gid < nq + 2 * nkv) { src = v; out = outv; loc = gid - nq - nkv; }
    else return;
    const int m = loc >> 7, c4 = loc & 127;
    float4 x = src[loc];
    bf4 hv, lv;
    split1(x.x, hv.a, lv.a); split1(x.y, hv.b, lv.b);
    split1(x.z, hv.c, lv.c); split1(x.w, hv.d, lv.d);
    __nv_bfloat16* base = out + (size_t)m * GK + c4 * 4;
    *(bf4*)(base) = hv;
    *(bf4*)(base + 512) = hv;
    *(bf4*)(base + 1024) = lv;
}

__global__ void split_wT_all(const float* __restrict__ W0, const float* __restrict__ W1,
                             const float* __restrict__ W2, const float* __restrict__ W3,
                             __nv_bfloat16* __restrict__ Wb) {
    const float* W = (blockIdx.z == 0) ? W0 : (blockIdx.z == 1) ? W1 : (blockIdx.z == 2) ? W2 : W3;
    __nv_bfloat16* outW = Wb + (size_t)blockIdx.z * WSTRIDE;
    __shared__ float t[32][33];
    const int k = blockIdx.y * 32 + threadIdx.y;
    const int n = blockIdx.x * 32 + threadIdx.x;
    t[threadIdx.y][threadIdx.x] = W[k * DMODEL + n];
    __syncthreads();
    const int n2 = blockIdx.x * 32 + threadIdx.y;
    const int k2 = blockIdx.y * 32 + threadIdx.x;
    const float x = t[threadIdx.x][threadIdx.y];
    __nv_bfloat16 h, l;
    split1(x, h, l);
    __nv_bfloat16* o = outW + (size_t)n2 * GK + k2;
    o[0] = h; o[512] = l; o[1024] = h;
}

// ---------------------------------------------------------------------------
// Sparse attention v2 (unchanged from R5): key-per-lane scores,
// float2-per-lane V accumulation.
// ---------------------------------------------------------------------------
#define QBLK 128
#define CTILE 48

__device__ __forceinline__ int floordiv_s(int a, int d) {
    return (a >= 0) ? (a / d) : -((-a + d - 1) / d);
}

__global__ __launch_bounds__(256) void sparse_attn_v2(const float* __restrict__ Q,
                                                      const float* __restrict__ Kp,
                                                      const float* __restrict__ Vp,
                                                      __nv_bfloat16* __restrict__ ctxb,
                                                      int Lq, int Lkv) {
    __shared__ float4 Ks4[CTILE][17];
    __shared__ float2 Vs2[CTILE][32];

    const int bh = blockIdx.y;
    const int b = bh / HEAD_NUM;
    const int h = bh % HEAD_NUM;
    const int c0 = blockIdx.x * QBLK;
    const int tid = threadIdx.x;
    const int wid = tid >> 5, lane = tid & 31;
    const int rlane = lane & 15;
    const int half = lane >> 4;

    const int colT0 = max(0, c0 / STRIDE - (R_SPAN - 1));

    for (int idx = tid; idx < CTILE * 16; idx += 256) {
        const int col = idx >> 4, d4 = idx & 15;
        if (colT0 + col < Lkv) {
            const size_t off = ((size_t)(b * Lkv + colT0 + col) * DMODEL) + h * 64 + d4 * 4;
            Ks4[col][d4] = __ldg((const float4*)(Kp + off));
        }
    }
    for (int idx = tid; idx < CTILE * 32; idx += 256) {
        const int col = idx >> 5, l2 = idx & 31;
        if (colT0 + col < Lkv) {
            const size_t off = ((size_t)(b * Lkv + colT0 + col) * DMODEL) + h * 64 + l2 * 2;
            Vs2[col][l2] = __ldg((const float2*)(Vp + off));
        }
    }
    __syncthreads();

    for (int step = 0; step < 8; step++) {
        const int cbase = c0 + wid * 16 + step * 2;
        const int c = cbase + half;

        const int fd = floordiv_s(SPAN - 1 - c, STRIDE);
        const int col = rlane - fd;
        const int row = c - STRIDE * col;
        const bool valid = (row >= 0) && (row < SPAN) && (col >= 0) && (col < Lkv);
        const int ii = min(max(col - colT0, 0), CTILE - 1);

        const float4* Qrow = (const float4*)(Q + ((size_t)(b * Lq + c) * DMODEL) + h * 64);
        float acc = 0.f;
        #pragma unroll
        for (int d4 = 0; d4 < 16; d4++) {
            const float4 qv = __ldg(Qrow + d4);
            const float4 kv = Ks4[ii][d4];
            acc += qv.x * kv.x + qv.y * kv.y + qv.z * kv.z + qv.w * kv.w;
        }
        const float sc = valid ? acc * 0.125f : -1e30f;

        float m = sc;
        #pragma unroll
        for (int off = 8; off > 0; off >>= 1)
            m = fmaxf(m, __shfl_xor_sync(0xffffffffu, m, off));
        const float e = valid ? __expf(sc - m) : 0.f;
        float s = e;
        #pragma unroll
        for (int off = 8; off > 0; off >>= 1)
            s += __shfl_xor_sync(0xffffffffu, s, off);
        const float w = e / s;

        #pragma unroll
        for (int qh = 0; qh < 2; qh++) {
            const int cq = cbase + qh;
            const int fdq = floordiv_s(SPAN - 1 - cq, STRIDE);
            float ox = 0.f, oy = 0.f;
            #pragma unroll
            for (int r = 0; r < R_SPAN; r++) {
                const float wr = __shfl_sync(0xffffffffu, w, qh * 16 + r);
                const int iir = min(max(r - fdq - colT0, 0), CTILE - 1);
                const float2 vv = Vs2[iir][lane];
                ox += wr * vv.x;
                oy += wr * vv.y;
            }
            __nv_bfloat16 hx, lx, hy, ly;
            split1(ox, hx, lx);
            split1(oy, hy, ly);
            __nv_bfloat16* base = ctxb + (size_t)(b * Lq + cq) * GK + h * DIM_V + 2 * lane;
            __nv_bfloat162 hp; hp.x = hx; hp.y = hy;
            __nv_bfloat162 lp; lp.x = lx; lp.y = ly;
            *(__nv_bfloat162*)(base) = hp;
            *(__nv_bfloat162*)(base + 512) = hp;
            *(__nv_bfloat162*)(base + 1024) = lp;
        }
    }
}

// ---------------------------------------------------------------------------
// Launch
// ---------------------------------------------------------------------------
extern "C" void kernel_launch(void* const* d_in, const int* in_sizes, int n_in,
                              void* d_out, int out_size) {
    const float* q    = (const float*)d_in[0];
    const float* k    = (const float*)d_in[1];
    const float* v    = (const float*)d_in[2];
    const float* Wq   = (const float*)d_in[3];
    const float* Wk   = (const float*)d_in[4];
    const float* Wv   = (const float*)d_in[5];
    const float* Wout = (const float*)d_in[6];
    float* out = (float*)d_out;

    const int Lq  = in_sizes[0] / (BATCH * DMODEL);   // 4096
    const int Lkv = in_sizes[1] / (BATCH * DMODEL);   // 1024
    const int Mq  = BATCH * Lq;    // 8192
    const int Mkv = BATCH * Lkv;   // 2048

    __nv_bfloat16 *gAb, *gKb, *gVb, *gWb;
    float *gQ, *gK, *gV;
    cudaGetSymbolAddress((void**)&gAb, g_Ab);
    cudaGetSymbolAddress((void**)&gKb, g_Kb);
    cudaGetSymbolAddress((void**)&gVb, g_Vb);
    cudaGetSymbolAddress((void**)&gWb, g_Wb4);
    cudaGetSymbolAddress((void**)&gQ, g_Q);
    cudaGetSymbolAddress((void**)&gK, g_K);
    cudaGetSymbolAddress((void**)&gV, g_V);

    cudaFuncSetAttribute(gemm_qkv, cudaFuncAttributeMaxDynamicSharedMemorySize, GEMM_SMEM);
    cudaFuncSetAttribute(gemm_one, cudaFuncAttributeMaxDynamicSharedMemorySize, GEMM_SMEM);

    split_wT_all<<<dim3(16, 16, 4), dim3(32, 32)>>>(Wq, Wk, Wv, Wout, gWb);

    const int tot = (Mq + 2 * Mkv) * 128;
    split_act_all<<<(tot + 255) / 256, 256>>>((const float4*)q, (const float4*)k,
                                              (const float4*)v, gAb, gKb, gVb, Mq, Mkv);

    gemm_qkv<<<384, 256, GEMM_SMEM>>>(gAb, gKb, gVb, gWb, gQ, gK, gV);

    sparse_attn_v2<<<dim3(Lq / QBLK, BATCH * HEAD_NUM), 256>>>(gQ, gK, gV, gAb, Lq, Lkv);

    gemm_one<<<dim3(4, Mq / 128), 256, GEMM_SMEM>>>(gAb, gWb + 3 * (size_t)WSTRIDE, out);
}